// round 5
// baseline (speedup 1.0000x reference)
#include <cuda_runtime.h>
#include <cuda_bf16.h>
#include <cstdint>

// FeaturesLoss via mma.sync bf16 m16n8k16 (compute_103-safe).
// Upper-triangle Gram, 128x128 tiles, 4-stage cp.async pipeline,
// fused loss epilogue on register fragments. Exact fp32 sq-norms.

#define BM 128
#define BN 128
#define BK 32
#define NSTAGES 4
#define NTHREADS 256
#define MAXN 4096
#define MAXD 512
#define SSTR 40  // smem row stride (bf16 elems) = 80 B, LDSM conflict-free

#define STAGE_OP_BYTES (BM * SSTR * 2)                 // 10240 per operand/stage
#define SM_A 0
#define SM_B (NSTAGES * STAGE_OP_BYTES)                // 40960
#define SM_SQA (2 * NSTAGES * STAGE_OP_BYTES)          // 81920
#define SM_SQB (SM_SQA + 512)
#define SM_LABA (SM_SQB + 512)
#define SM_LABB (SM_LABA + 512)
#define SM_RED (SM_LABB + 512)                          // 8*4*3 bytes reduction
#define SMEM_TOTAL (SM_RED + 128)

__device__ float g_sq[MAXN];
__device__ __align__(16) __nv_bfloat16 g_Xbf[MAXN * MAXD];
__device__ double g_sum1;
__device__ double g_sum2;
__device__ unsigned long long g_cnt;

__device__ __forceinline__ uint32_t smem_u32(const void* p) {
    uint32_t a;
    asm("{ .reg .u64 t; cvta.to.shared.u64 t, %1; cvt.u32.u64 %0, t; }"
        : "=r"(a) : "l"(p));
    return a;
}

#define CP_ASYNC16(dst_u32, src) \
    asm volatile("cp.async.cg.shared.global [%0], [%1], 16;" :: "r"(dst_u32), "l"(src))
#define CP_COMMIT() asm volatile("cp.async.commit_group;" ::: "memory")
#define CP_WAIT2()  asm volatile("cp.async.wait_group 2;" ::: "memory")
#define CP_WAIT0()  asm volatile("cp.async.wait_group 0;" ::: "memory")

#define LDSM_X4(r0, r1, r2, r3, a)                                        \
    asm volatile("ldmatrix.sync.aligned.m8n8.x4.shared.b16 "              \
                 "{%0,%1,%2,%3}, [%4];"                                   \
                 : "=r"(r0), "=r"(r1), "=r"(r2), "=r"(r3) : "r"(a))

#define MMA16816(c, a0, a1, a2, a3, b0, b1)                               \
    asm volatile("mma.sync.aligned.m16n8k16.row.col.f32.bf16.bf16.f32 "   \
                 "{%0,%1,%2,%3}, {%4,%5,%6,%7}, {%8,%9}, {%0,%1,%2,%3};"  \
                 : "+f"((c)[0]), "+f"((c)[1]), "+f"((c)[2]), "+f"((c)[3]) \
                 : "r"(a0), "r"(a1), "r"(a2), "r"(a3), "r"(b0), "r"(b1))

// ---------------------------------------------------------------------------
// Kernel A: X -> bf16 + exact fp32 row norms. One row per 128-thread block.
// ---------------------------------------------------------------------------
__global__ void __launch_bounds__(128) convert_kernel(const float* __restrict__ X,
                                                      int n, int d) {
    if (blockIdx.x == 0 && threadIdx.x == 0) {
        g_sum1 = 0.0;
        g_sum2 = 0.0;
        g_cnt = 0ull;
    }
    const int row = blockIdx.x;
    const int t = threadIdx.x;
    const float4* src = reinterpret_cast<const float4*>(X + (size_t)row * d);
    __nv_bfloat162* dst = reinterpret_cast<__nv_bfloat162*>(g_Xbf + (size_t)row * d);
    float s = 0.0f;
    const int n4 = d / 4;  // 128 for d=512
    for (int c4 = t; c4 < n4; c4 += 128) {
        float4 v = src[c4];
        s = fmaf(v.x, v.x, fmaf(v.y, v.y, fmaf(v.z, v.z, fmaf(v.w, v.w, s))));
        __nv_bfloat162 p0, p1;
        p0.x = __float2bfloat16(v.x);
        p0.y = __float2bfloat16(v.y);
        p1.x = __float2bfloat16(v.z);
        p1.y = __float2bfloat16(v.w);
        dst[c4 * 2 + 0] = p0;
        dst[c4 * 2 + 1] = p1;
    }
#pragma unroll
    for (int o = 16; o > 0; o >>= 1) s += __shfl_down_sync(0xffffffffu, s, o);
    __shared__ float red[4];
    if ((t & 31) == 0) red[t >> 5] = s;
    __syncthreads();
    if (t == 0) g_sq[row] = red[0] + red[1] + red[2] + red[3];
}

// ---------------------------------------------------------------------------
// Kernel B: upper-triangular mma.sync Gram + fused loss epilogue.
// ---------------------------------------------------------------------------
__global__ void __launch_bounds__(NTHREADS, 2) pair_kernel(
    const int* __restrict__ lab, const float* __restrict__ marginp,
    int n, int d, int nt) {
    extern __shared__ __align__(1024) char smem[];
    const uint32_t sbase = smem_u32(smem);

    float* sqA = reinterpret_cast<float*>(smem + SM_SQA);
    float* sqB = reinterpret_cast<float*>(smem + SM_SQB);
    int* labA = reinterpret_cast<int*>(smem + SM_LABA);
    int* labB = reinterpret_cast<int*>(smem + SM_LABB);

    const int tid = threadIdx.x;
    const int wid = tid >> 5, lane = tid & 31;
    const int warpM = wid & 3;   // 4 warps over M: 32 rows each
    const int warpN = wid >> 2;  // 2 warps over N: 64 cols each

    // Decode linear block id -> (br, bc), br <= bc.
    int b = blockIdx.x, br = 0, rl = nt;
    while (b >= rl) {
        b -= rl;
        rl--;
        br++;
    }
    const int bc = br + b;
    const int rowBase = br * BM;
    const int colBase = bc * BN;

    for (int i = tid; i < BM; i += NTHREADS) {
        sqA[i] = g_sq[rowBase + i];
        sqB[i] = g_sq[colBase + i];
        labA[i] = lab[rowBase + i];
        labB[i] = lab[colBase + i];
    }

    const __nv_bfloat16* __restrict__ Xb = g_Xbf;

    // Loader: chunk c (BK=32 cols) into stage c&3. No commit (caller commits).
    auto load_chunk = [&](int c) {
        const int s = c & (NSTAGES - 1);
        const uint32_t aBase = sbase + SM_A + (uint32_t)s * STAGE_OP_BYTES;
        const uint32_t bBase = sbase + SM_B + (uint32_t)s * STAGE_OP_BYTES;
#pragma unroll
        for (int l = 0; l < 2; l++) {
            int flat = tid + l * NTHREADS;  // 0..511
            int r = flat >> 2;              // row 0..127
            int kc = flat & 3;              // 16B piece in row
            uint32_t off = (uint32_t)r * (SSTR * 2) + (uint32_t)kc * 16;
            const __nv_bfloat16* ga = Xb + (size_t)(rowBase + r) * d + c * BK + kc * 8;
            const __nv_bfloat16* gb = Xb + (size_t)(colBase + r) * d + c * BK + kc * 8;
            CP_ASYNC16(aBase + off, ga);
            CP_ASYNC16(bBase + off, gb);
        }
    };

    float acc[2][8][4];
#pragma unroll
    for (int mt = 0; mt < 2; mt++)
#pragma unroll
        for (int ntile = 0; ntile < 8; ntile++)
#pragma unroll
            for (int e = 0; e < 4; e++) acc[mt][ntile][e] = 0.0f;

    const uint32_t laneRow = (uint32_t)(lane & 15) * (SSTR * 2);
    const uint32_t laneK = (uint32_t)(lane >> 4) * 16;
    const uint32_t aLane =
        sbase + SM_A + (uint32_t)(warpM * 32) * (SSTR * 2) + laneRow + laneK;
    const uint32_t bLane =
        sbase + SM_B + (uint32_t)(warpN * 64) * (SSTR * 2) + laneRow + laneK;

    const int nChunks = d / BK;  // 16 for d=512

    // Prologue: 3 chunks in flight.
#pragma unroll
    for (int c = 0; c < 3; c++) {
        load_chunk(c);
        CP_COMMIT();
    }

    for (int c = 0; c < nChunks; c++) {
        CP_WAIT2();      // chunk c resident (2 younger groups may be pending)
        __syncthreads(); // all warps done with stage (c-1)&3; chunk c visible

        if (c + 3 < nChunks) load_chunk(c + 3);
        CP_COMMIT();     // always commit (possibly empty) to keep counts aligned

        const uint32_t aBase = aLane + (uint32_t)(c & 3) * STAGE_OP_BYTES;
        const uint32_t bBase = bLane + (uint32_t)(c & 3) * STAGE_OP_BYTES;

        uint32_t a[2][2][4];
#pragma unroll
        for (int mt = 0; mt < 2; mt++)
#pragma unroll
            for (int ks = 0; ks < 2; ks++)
                LDSM_X4(a[mt][ks][0], a[mt][ks][1], a[mt][ks][2], a[mt][ks][3],
                        aBase + (uint32_t)mt * 16 * (SSTR * 2) + (uint32_t)ks * 32);

#pragma unroll
        for (int ks = 0; ks < 2; ks++) {
#pragma unroll
            for (int ntp = 0; ntp < 4; ntp++) {
                uint32_t r0, r1, r2, r3;
                LDSM_X4(r0, r1, r2, r3,
                        bBase + (uint32_t)ntp * 16 * (SSTR * 2) + (uint32_t)ks * 32);
#pragma unroll
                for (int mt = 0; mt < 2; mt++) {
                    MMA16816(acc[mt][2 * ntp + 0], a[mt][ks][0], a[mt][ks][1],
                             a[mt][ks][2], a[mt][ks][3], r0, r2);
                    MMA16816(acc[mt][2 * ntp + 1], a[mt][ks][0], a[mt][ks][1],
                             a[mt][ks][2], a[mt][ks][3], r1, r3);
                }
            }
        }
    }
    CP_WAIT0();

    // Fused epilogue on C fragments.
    const float margin = *marginp;
    const bool diag = (br == bc);
    float s1 = 0.0f, s2 = 0.0f;
    unsigned int cnt = 0;
#pragma unroll
    for (int mt = 0; mt < 2; mt++) {
        const int i0 = warpM * 32 + mt * 16 + (lane >> 2);
#pragma unroll
        for (int half = 0; half < 2; half++) {
            const int iloc = i0 + half * 8;
            const int gi = rowBase + iloc;
            const float sqi = sqA[iloc];
            const int li = labA[iloc];
#pragma unroll
            for (int ntile = 0; ntile < 8; ntile++) {
#pragma unroll
                for (int e = 0; e < 2; e++) {
                    const int jloc = warpN * 64 + ntile * 8 + (lane & 3) * 2 + e;
                    const int gj = colBase + jloc;
                    float w = 2.0f;
                    if (diag) w = (gi > gj) ? 0.0f : ((gi == gj) ? 1.0f : 2.0f);
                    if (w != 0.0f) {
                        float D = sqi + sqB[jloc] - 2.0f * acc[mt][ntile][half * 2 + e];
                        D = fmaxf(D, 0.0f);
                        if (li == labB[jloc]) {
                            s1 += w * D;
                            cnt += (unsigned int)w;
                        } else {
                            s2 += w * fmaxf(0.0f, margin - D);
                        }
                    }
                }
            }
        }
    }

    // Block reduction -> double atomics.
#pragma unroll
    for (int o = 16; o > 0; o >>= 1) {
        s1 += __shfl_down_sync(0xffffffffu, s1, o);
        s2 += __shfl_down_sync(0xffffffffu, s2, o);
        cnt += __shfl_down_sync(0xffffffffu, cnt, o);
    }
    float* r1 = reinterpret_cast<float*>(smem + SM_RED);
    float* r2 = r1 + 8;
    unsigned int* rc = reinterpret_cast<unsigned int*>(r2 + 8);
    if (lane == 0) {
        r1[wid] = s1;
        r2[wid] = s2;
        rc[wid] = cnt;
    }
    __syncthreads();
    if (tid == 0) {
        double t1 = 0.0, t2 = 0.0;
        unsigned int tc = 0;
#pragma unroll
        for (int w = 0; w < 8; w++) {
            t1 += (double)r1[w];
            t2 += (double)r2[w];
            tc += rc[w];
        }
        atomicAdd(&g_sum1, t1);
        atomicAdd(&g_sum2, t2);
        atomicAdd(&g_cnt, (unsigned long long)tc);
    }
}

// ---------------------------------------------------------------------------
// Kernel C: final scalar combine.
// ---------------------------------------------------------------------------
__global__ void finalize_kernel(float* out, int n) {
    double zn1 = (double)g_cnt;
    double zn2 = (double)n * (double)n - zn1;
    out[0] = (float)(0.5 * (g_sum1 / zn1 + g_sum2 / zn2));
}

extern "C" void kernel_launch(void* const* d_in, const int* in_sizes, int n_in,
                              void* d_out, int out_size) {
    const float* X = (const float*)d_in[0];
    const int* lab = (const int*)d_in[1];
    const float* marginp = (const float*)d_in[2];
    float* out = (float*)d_out;

    int n = in_sizes[1];
    int d = in_sizes[0] / n;

    cudaFuncSetAttribute(pair_kernel,
                         cudaFuncAttributeMaxDynamicSharedMemorySize, SMEM_TOTAL);

    convert_kernel<<<n, 128>>>(X, n, d);

    int nt = (n + BM - 1) / BM;
    int nb = nt * (nt + 1) / 2;
    pair_kernel<<<nb, NTHREADS, SMEM_TOTAL>>>(lab, marginp, n, d, nt);

    finalize_kernel<<<1, 1>>>(out, n);
}

// round 6
// speedup vs baseline: 1.0472x; 1.0472x over previous
#include <cuda_runtime.h>
#include <cuda_bf16.h>
#include <cstdint>

// FeaturesLoss via mma.sync e4m3 m16n8k32 (sm_89-baseline PTX, compute_103-safe).
// Upper-triangle Gram, 128x128 tiles, 2-stage cp.async (R4-best shape),
// fused loss epilogue on register fragments. Exact fp32 sq-norms.

#define BM 128
#define BN 128
#define BK 64            // fp8 elems (bytes) per K-chunk
#define NTHREADS 256
#define MAXN 4096
#define MAXD 512
#define SSTRB 80         // smem row stride bytes (64+16): conflict-free 16B granules

#define STAGE_OP_BYTES (BM * SSTRB)  // 10240 per operand per stage

__device__ float g_sq[MAXN];
__device__ __align__(16) uint8_t g_Xf8[MAXN * MAXD];
__device__ double g_sum1;
__device__ double g_sum2;
__device__ unsigned long long g_cnt;

__device__ __forceinline__ uint32_t smem_u32(const void* p) {
    uint32_t a;
    asm("{ .reg .u64 t; cvta.to.shared.u64 t, %1; cvt.u32.u64 %0, t; }"
        : "=r"(a) : "l"(p));
    return a;
}

#define CP_ASYNC16(dst_u32, src) \
    asm volatile("cp.async.cg.shared.global [%0], [%1], 16;" :: "r"(dst_u32), "l"(src))
#define CP_COMMIT() asm volatile("cp.async.commit_group;" ::: "memory")
#define CP_WAIT0()  asm volatile("cp.async.wait_group 0;" ::: "memory")

#define LDSM_X4(r0, r1, r2, r3, a)                                        \
    asm volatile("ldmatrix.sync.aligned.m8n8.x4.shared.b16 "              \
                 "{%0,%1,%2,%3}, [%4];"                                   \
                 : "=r"(r0), "=r"(r1), "=r"(r2), "=r"(r3) : "r"(a))

#define MMA16832(c, a0, a1, a2, a3, b0, b1)                               \
    asm volatile("mma.sync.aligned.m16n8k32.row.col.f32.e4m3.e4m3.f32 "   \
                 "{%0,%1,%2,%3}, {%4,%5,%6,%7}, {%8,%9}, {%0,%1,%2,%3};"  \
                 : "+f"((c)[0]), "+f"((c)[1]), "+f"((c)[2]), "+f"((c)[3]) \
                 : "r"(a0), "r"(a1), "r"(a2), "r"(a3), "r"(b0), "r"(b1))

__device__ __forceinline__ uint32_t pack_e4m3x4(float4 v) {
    uint16_t lo, hi;
    asm("cvt.rn.satfinite.e4m3x2.f32 %0, %1, %2;" : "=h"(lo) : "f"(v.y), "f"(v.x));
    asm("cvt.rn.satfinite.e4m3x2.f32 %0, %1, %2;" : "=h"(hi) : "f"(v.w), "f"(v.z));
    return (uint32_t)lo | ((uint32_t)hi << 16);
}

// ---------------------------------------------------------------------------
// Kernel A: X -> e4m3 + exact fp32 row norms. One warp per row, MLP=4.
// ---------------------------------------------------------------------------
__global__ void __launch_bounds__(256) convert_kernel(const float* __restrict__ X,
                                                      int n, int d) {
    if (blockIdx.x == 0 && threadIdx.x == 0) {
        g_sum1 = 0.0;
        g_sum2 = 0.0;
        g_cnt = 0ull;
    }
    const int w = threadIdx.x >> 5, l = threadIdx.x & 31;
    const int row = blockIdx.x * 8 + w;
    if (row >= n) return;
    const float4* src = reinterpret_cast<const float4*>(X + (size_t)row * d);
    uint32_t* dst = reinterpret_cast<uint32_t*>(g_Xf8 + (size_t)row * d);
    float s = 0.0f;
    if (d == 512) {  // fast path: 128 float4 per row, 4 per lane, batched loads
        float4 v[4];
#pragma unroll
        for (int i = 0; i < 4; i++) v[i] = src[l + 32 * i];
#pragma unroll
        for (int i = 0; i < 4; i++) {
            s = fmaf(v[i].x, v[i].x,
                     fmaf(v[i].y, v[i].y,
                          fmaf(v[i].z, v[i].z, fmaf(v[i].w, v[i].w, s))));
            dst[l + 32 * i] = pack_e4m3x4(v[i]);
        }
    } else {
        for (int c4 = l; c4 * 4 < d; c4 += 32) {
            float4 v = src[c4];
            s = fmaf(v.x, v.x, fmaf(v.y, v.y, fmaf(v.z, v.z, fmaf(v.w, v.w, s))));
            dst[c4] = pack_e4m3x4(v);
        }
    }
#pragma unroll
    for (int o = 16; o > 0; o >>= 1) s += __shfl_down_sync(0xffffffffu, s, o);
    if (l == 0) g_sq[row] = s;
}

// ---------------------------------------------------------------------------
// Kernel B: upper-triangular fp8 mma.sync Gram + fused loss epilogue.
// ---------------------------------------------------------------------------
__global__ void __launch_bounds__(NTHREADS, 2) pair_kernel(
    const int* __restrict__ lab, const float* __restrict__ marginp,
    int n, int d, int nt) {
    __shared__ __align__(1024) uint8_t As[2][STAGE_OP_BYTES];
    __shared__ __align__(1024) uint8_t Bs[2][STAGE_OP_BYTES];
    __shared__ float sqA[BM], sqB[BN];
    __shared__ int labA[BM], labB[BN];

    const int tid = threadIdx.x;
    const int wid = tid >> 5, lane = tid & 31;
    const int warpM = wid & 3;   // 4 warps over M: 32 rows each
    const int warpN = wid >> 2;  // 2 warps over N: 64 cols each

    // Decode linear block id -> (br, bc), br <= bc.
    int b = blockIdx.x, br = 0, rl = nt;
    while (b >= rl) {
        b -= rl;
        rl--;
        br++;
    }
    const int bc = br + b;
    const int rowBase = br * BM;
    const int colBase = bc * BN;

    for (int i = tid; i < BM; i += NTHREADS) {
        sqA[i] = g_sq[rowBase + i];
        sqB[i] = g_sq[colBase + i];
        labA[i] = lab[rowBase + i];
        labB[i] = lab[colBase + i];
    }

    const uint32_t aS0 = smem_u32(&As[0][0]);
    const uint32_t bS0 = smem_u32(&Bs[0][0]);
    const uint8_t* __restrict__ Xb = g_Xf8;

    // Loader: chunk c (BK=64 bytes) into stage c&1. 512 16B-pieces per operand.
    auto load_chunk = [&](int c) {
        const uint32_t aBase = aS0 + (uint32_t)(c & 1) * STAGE_OP_BYTES;
        const uint32_t bBase = bS0 + (uint32_t)(c & 1) * STAGE_OP_BYTES;
#pragma unroll
        for (int l = 0; l < 2; l++) {
            int flat = tid + l * NTHREADS;  // 0..511
            int r = flat >> 2;              // row 0..127
            int kc = flat & 3;              // 16B piece
            uint32_t off = (uint32_t)r * SSTRB + (uint32_t)kc * 16;
            const uint8_t* ga = Xb + (size_t)(rowBase + r) * d + c * BK + kc * 16;
            const uint8_t* gb = Xb + (size_t)(colBase + r) * d + c * BK + kc * 16;
            CP_ASYNC16(aBase + off, ga);
            CP_ASYNC16(bBase + off, gb);
        }
        CP_COMMIT();
    };

    float acc[2][8][4];
#pragma unroll
    for (int mt = 0; mt < 2; mt++)
#pragma unroll
        for (int ntile = 0; ntile < 8; ntile++)
#pragma unroll
            for (int e = 0; e < 4; e++) acc[mt][ntile][e] = 0.0f;

    // ldmatrix lane addressing: rows = lane&15, k-half = (lane>>4)*16 bytes.
    const uint32_t laneRow = (uint32_t)(lane & 15) * SSTRB;
    const uint32_t laneK = (uint32_t)(lane >> 4) * 16;
    const uint32_t aLane = (uint32_t)(warpM * 32) * SSTRB + laneRow + laneK;
    const uint32_t bLane = (uint32_t)(warpN * 64) * SSTRB + laneRow + laneK;

    const int nChunks = d / BK;  // 8 for d=512
    load_chunk(0);

    for (int c = 0; c < nChunks; c++) {
        CP_WAIT0();
        __syncthreads();
        if (c + 1 < nChunks) load_chunk(c + 1);

        const uint32_t aBase = aS0 + (uint32_t)(c & 1) * STAGE_OP_BYTES + aLane;
        const uint32_t bBase = bS0 + (uint32_t)(c & 1) * STAGE_OP_BYTES + bLane;

        // A fragments: 2 m-tiles x 2 k32-steps (each step = 32 bytes).
        uint32_t a[2][2][4];
#pragma unroll
        for (int mt = 0; mt < 2; mt++)
#pragma unroll
            for (int ks = 0; ks < 2; ks++)
                LDSM_X4(a[mt][ks][0], a[mt][ks][1], a[mt][ks][2], a[mt][ks][3],
                        aBase + (uint32_t)mt * 16 * SSTRB + (uint32_t)ks * 32);

#pragma unroll
        for (int ks = 0; ks < 2; ks++) {
#pragma unroll
            for (int ntp = 0; ntp < 4; ntp++) {
                uint32_t r0, r1, r2, r3;
                LDSM_X4(r0, r1, r2, r3,
                        bBase + (uint32_t)ntp * 16 * SSTRB + (uint32_t)ks * 32);
                // even n-tile fragment {r0,r2}, odd {r1,r3}
#pragma unroll
                for (int mt = 0; mt < 2; mt++) {
                    MMA16832(acc[mt][2 * ntp + 0], a[mt][ks][0], a[mt][ks][1],
                             a[mt][ks][2], a[mt][ks][3], r0, r2);
                    MMA16832(acc[mt][2 * ntp + 1], a[mt][ks][0], a[mt][ks][1],
                             a[mt][ks][2], a[mt][ks][3], r1, r3);
                }
            }
        }
        __syncthreads();
    }

    // Fused epilogue on C fragments (same layout as m16n8k16).
    const float margin = *marginp;
    const bool diag = (br == bc);
    float s1 = 0.0f, s2 = 0.0f;
    unsigned int cnt = 0;
#pragma unroll
    for (int mt = 0; mt < 2; mt++) {
        const int i0 = warpM * 32 + mt * 16 + (lane >> 2);
#pragma unroll
        for (int half = 0; half < 2; half++) {
            const int iloc = i0 + half * 8;
            const int gi = rowBase + iloc;
            const float sqi = sqA[iloc];
            const int li = labA[iloc];
#pragma unroll
            for (int ntile = 0; ntile < 8; ntile++) {
#pragma unroll
                for (int e = 0; e < 2; e++) {
                    const int jloc = warpN * 64 + ntile * 8 + (lane & 3) * 2 + e;
                    const int gj = colBase + jloc;
                    float w = 2.0f;
                    if (diag) w = (gi > gj) ? 0.0f : ((gi == gj) ? 1.0f : 2.0f);
                    if (w != 0.0f) {
                        float D = sqi + sqB[jloc] - 2.0f * acc[mt][ntile][half * 2 + e];
                        D = fmaxf(D, 0.0f);
                        if (li == labB[jloc]) {
                            s1 += w * D;
                            cnt += (unsigned int)w;
                        } else {
                            s2 += w * fmaxf(0.0f, margin - D);
                        }
                    }
                }
            }
        }
    }

    // Block reduction -> double atomics.
#pragma unroll
    for (int o = 16; o > 0; o >>= 1) {
        s1 += __shfl_down_sync(0xffffffffu, s1, o);
        s2 += __shfl_down_sync(0xffffffffu, s2, o);
        cnt += __shfl_down_sync(0xffffffffu, cnt, o);
    }
    __shared__ float r1[8], r2[8];
    __shared__ unsigned int rc[8];
    if (lane == 0) {
        r1[wid] = s1;
        r2[wid] = s2;
        rc[wid] = cnt;
    }
    __syncthreads();
    if (tid == 0) {
        double t1 = 0.0, t2 = 0.0;
        unsigned int tc = 0;
#pragma unroll
        for (int w = 0; w < 8; w++) {
            t1 += (double)r1[w];
            t2 += (double)r2[w];
            tc += rc[w];
        }
        atomicAdd(&g_sum1, t1);
        atomicAdd(&g_sum2, t2);
        atomicAdd(&g_cnt, (unsigned long long)tc);
    }
}

// ---------------------------------------------------------------------------
// Kernel C: final scalar combine.
// ---------------------------------------------------------------------------
__global__ void finalize_kernel(float* out, int n) {
    double zn1 = (double)g_cnt;
    double zn2 = (double)n * (double)n - zn1;
    out[0] = (float)(0.5 * (g_sum1 / zn1 + g_sum2 / zn2));
}

extern "C" void kernel_launch(void* const* d_in, const int* in_sizes, int n_in,
                              void* d_out, int out_size) {
    const float* X = (const float*)d_in[0];
    const int* lab = (const int*)d_in[1];
    const float* marginp = (const float*)d_in[2];
    float* out = (float*)d_out;

    int n = in_sizes[1];
    int d = in_sizes[0] / n;

    convert_kernel<<<(n + 7) / 8, 256>>>(X, n, d);

    int nt = (n + BM - 1) / BM;
    int nb = nt * (nt + 1) / 2;
    pair_kernel<<<nb, NTHREADS>>>(lab, marginp, n, d, nt);

    finalize_kernel<<<1, 1>>>(out, n);
}